// round 4
// baseline (speedup 1.0000x reference)
#include <cuda_runtime.h>
#include <cuda_bf16.h>

#define TENC 48
#define TDEC 24
#define DSTEPS 30
#define HD 128
#define NF1 17
#define NF2 129
#define K1 145
#define KP1 152
#define K2 257
#define KP2 264
#define KD 256
#define KPD 256
#define G 8
#define NCTA 128
#define NTH 512
#define NG 512
#define BTOT 1024
#define HCT_STR 10

typedef unsigned long long u64;

// ---------------- device scratch (allocation-free) ----------------
__device__ float g_WtT1[NG * KP1];            // [n][k] zero-padded
__device__ float g_WtT2[NG * KP2];
__device__ float g_WtTd[NG * KPD];
__device__ float g_Wet1[256 * TENC];
__device__ float g_Wet2[256 * TENC];
__device__ float g_Wdt[256 * HD];             // [k][j]
__device__ float g_Udt[HD * HD];
__device__ float g_b1[NG], g_b2[NG], g_bd[NG];
__device__ float g_pre1[BTOT * TENC * NF1];           // [b][s][f] fp32
__device__ __nv_bfloat16 g_pre2h[BTOT * TENC * NF2];  // [b][s][f] bf16
__device__ float g_mid[BTOT * TENC * NF2];            // [b][t][f] (f=128 label)
__device__ float g_fin[BTOT * TENC * HD];             // [b][t][j]
__device__ __nv_bfloat16 g_udTh[BTOT * HD * TENC];    // [b][j][t] bf16

// ---------------- math helpers ----------------
__device__ __forceinline__ float tanha(float x) {
    float y; asm("tanh.approx.f32 %0, %1;" : "=f"(y) : "f"(x)); return y;
}
__device__ __forceinline__ float siga(float x) {
    return fmaf(tanha(0.5f * x), 0.5f, 0.5f);
}
__device__ __forceinline__ u64 fma2(u64 a, u64 b, u64 c) {
    u64 d; asm("fma.rn.f32x2 %0, %1, %2, %3;" : "=l"(d) : "l"(a), "l"(b), "l"(c)); return d;
}
__device__ __forceinline__ u64 dup2(float x) {
    u64 d; unsigned r = __float_as_uint(x);
    asm("mov.b64 %0, {%1, %1};" : "=l"(d) : "r"(r)); return d;
}
__device__ __forceinline__ float2 unpack2(u64 a) {
    unsigned l, h;
    asm("mov.b64 {%0, %1}, %2;" : "=r"(l), "=r"(h) : "l"(a));
    return make_float2(__uint_as_float(l), __uint_as_float(h));
}

__device__ __forceinline__ void warp_softmax(const float* score_row, float* alpha_row,
                                             int F, int lane) {
    float mx = -1e30f;
    for (int f = lane; f < F; f += 32) mx = fmaxf(mx, score_row[f]);
#pragma unroll
    for (int o = 16; o; o >>= 1) mx = fmaxf(mx, __shfl_xor_sync(0xffffffffu, mx, o));
    float sm = 0.f;
    for (int f = lane; f < F; f += 32) {
        float e = __expf(score_row[f] - mx);
        alpha_row[f] = e;
        sm += e;
    }
#pragma unroll
    for (int o = 16; o; o >>= 1) sm += __shfl_xor_sync(0xffffffffu, sm, o);
    float inv = __fdividef(1.f, sm);
    for (int f = lane; f < F; f += 32) alpha_row[f] *= inv;
}

// gate GEMM with K split across both thread halves.
// WtT: [n][KP] global (zero-padded). inpair smem [KP][8]. gates smem [8][NG].
// pg smem [NG][9] partials. bias smem [NG]. Caller syncs after.
template <int KP>
__device__ __forceinline__ void gates_gemm2(const float* __restrict__ WtT,
                                            const float* __restrict__ bias,
                                            const float* __restrict__ inpair,
                                            float* __restrict__ gates,
                                            float* __restrict__ pg, int tid) {
    const int half = tid >> 8;
    const int lt = tid & 255;
    const int n0 = lt * 2;
    constexpr int KH = KP / 2;
    const int k0 = half * KH;
    u64 a0 = 0, a1 = 0, a2 = 0, a3 = 0, a4 = 0, a5 = 0, a6 = 0, a7 = 0;
    const float* w0p = WtT + (size_t)n0 * KP + k0;
    const float* w1p = w0p + KP;
    const float* ipp = inpair + k0 * G;
#pragma unroll 2
    for (int kk = 0; kk < KH; kk += 4) {
        float4 wa = *(const float4*)(w0p + kk);
        float4 wb = *(const float4*)(w1p + kk);
        const float* wav = (const float*)&wa;
        const float* wbv = (const float*)&wb;
        const float* ip = ipp + kk * G;
#pragma unroll
        for (int q = 0; q < 4; q++) {
            ulonglong2 iab = *(const ulonglong2*)(ip + q * G);
            ulonglong2 icd = *(const ulonglong2*)(ip + q * G + 4);
            u64 w0 = dup2(wav[q]), w1 = dup2(wbv[q]);
            a0 = fma2(w0, iab.x, a0); a1 = fma2(w0, iab.y, a1);
            a2 = fma2(w0, icd.x, a2); a3 = fma2(w0, icd.y, a3);
            a4 = fma2(w1, iab.x, a4); a5 = fma2(w1, iab.y, a5);
            a6 = fma2(w1, icd.x, a6); a7 = fma2(w1, icd.y, a7);
        }
    }
    if (half) {
        float* pp = pg + n0 * 9;
        float2 r;
        r = unpack2(a0); pp[0] = r.x; pp[1] = r.y;
        r = unpack2(a1); pp[2] = r.x; pp[3] = r.y;
        r = unpack2(a2); pp[4] = r.x; pp[5] = r.y;
        r = unpack2(a3); pp[6] = r.x; pp[7] = r.y;
        pp += 9;
        r = unpack2(a4); pp[0] = r.x; pp[1] = r.y;
        r = unpack2(a5); pp[2] = r.x; pp[3] = r.y;
        r = unpack2(a6); pp[4] = r.x; pp[5] = r.y;
        r = unpack2(a7); pp[6] = r.x; pp[7] = r.y;
    }
    __syncthreads();
    if (!half) {
        const float* pp = pg + n0 * 9;
        const float* pq = pp + 9;
        float b0 = bias[n0], b1 = bias[n0 + 1];
        float2 r;
        r = unpack2(a0); gates[0*NG+n0] = r.x + pp[0] + b0; gates[1*NG+n0] = r.y + pp[1] + b0;
        r = unpack2(a1); gates[2*NG+n0] = r.x + pp[2] + b0; gates[3*NG+n0] = r.y + pp[3] + b0;
        r = unpack2(a2); gates[4*NG+n0] = r.x + pp[4] + b0; gates[5*NG+n0] = r.y + pp[5] + b0;
        r = unpack2(a3); gates[6*NG+n0] = r.x + pp[6] + b0; gates[7*NG+n0] = r.y + pp[7] + b0;
        r = unpack2(a4); gates[0*NG+n0+1] = r.x + pq[0] + b1; gates[1*NG+n0+1] = r.y + pq[1] + b1;
        r = unpack2(a5); gates[2*NG+n0+1] = r.x + pq[2] + b1; gates[3*NG+n0+1] = r.y + pq[3] + b1;
        r = unpack2(a6); gates[4*NG+n0+1] = r.x + pq[4] + b1; gates[5*NG+n0+1] = r.y + pq[5] + b1;
        r = unpack2(a7); gates[6*NG+n0+1] = r.x + pq[6] + b1; gates[7*NG+n0+1] = r.y + pq[7] + b1;
    }
}

// ---------------- setup ----------------
__global__ void setup_kernel(
    const float* __restrict__ e1_Wih, const float* __restrict__ e1_Whh,
    const float* __restrict__ e2_Wih, const float* __restrict__ e2_Whh,
    const float* __restrict__ d_Wih,  const float* __restrict__ d_Whh,
    const float* __restrict__ We1,    const float* __restrict__ We2,
    const float* __restrict__ Wd,     const float* __restrict__ Ud,
    const float* __restrict__ e1_bih, const float* __restrict__ e1_bhh,
    const float* __restrict__ e2_bih, const float* __restrict__ e2_bhh,
    const float* __restrict__ d_bih,  const float* __restrict__ d_bhh) {
    int tid = blockIdx.x * blockDim.x + threadIdx.x;
    int nt = gridDim.x * blockDim.x;
    for (int i = tid; i < NG * KP1; i += nt) {
        int n = i / KP1, k = i % KP1;
        float v = 0.f;
        if (k < K1) v = (k < NF1) ? e1_Wih[n * NF1 + k] : e1_Whh[n * HD + (k - NF1)];
        g_WtT1[i] = v;
    }
    for (int i = tid; i < NG * KP2; i += nt) {
        int n = i / KP2, k = i % KP2;
        float v = 0.f;
        if (k < K2) v = (k < NF2) ? e2_Wih[n * NF2 + k] : e2_Whh[n * HD + (k - NF2)];
        g_WtT2[i] = v;
    }
    for (int i = tid; i < NG * KPD; i += nt) {
        int n = i / KPD, k = i % KPD;
        g_WtTd[i] = (k < HD) ? d_Wih[n * HD + k] : d_Whh[n * HD + (k - HD)];
    }
    for (int i = tid; i < 256 * TENC; i += nt) {
        int k = i / TENC, ss = i % TENC;
        g_Wet1[i] = We1[ss * 256 + k];
        g_Wet2[i] = We2[ss * 256 + k];
    }
    for (int i = tid; i < 256 * HD; i += nt) {
        int k = i / HD, j = i % HD;
        g_Wdt[i] = Wd[j * 256 + k];
    }
    for (int i = tid; i < HD * HD; i += nt) {
        int k = i / HD, j = i % HD;
        g_Udt[i] = Ud[j * HD + k];
    }
    for (int i = tid; i < NG; i += nt) {
        g_b1[i] = e1_bih[i] + e1_bhh[i];
        g_b2[i] = e2_bih[i] + e2_bhh[i];
        g_bd[i] = d_bih[i] + d_bhh[i];
    }
}

// ---------------- pre1 ----------------
__global__ __launch_bounds__(256) void pre1_kernel(
    const float* __restrict__ inp, const float* __restrict__ lab,
    const float* __restrict__ Ue1, const float* __restrict__ Ue1b) {
    __shared__ float xs[TENC * NF1];
    __shared__ float ue[TENC * TENC];
    int b = blockIdx.x, tid = threadIdx.x;
    for (int i = tid; i < TENC * NF1; i += 256) {
        int t = i / NF1, f = i % NF1;
        xs[i] = inp[((size_t)b * TENC + t) * 18 + f + 1];
    }
    for (int i = tid; i < TENC * TENC; i += 256) ue[i] = Ue1[i];
    for (int i = tid; i < TENC; i += 256)
        g_mid[((size_t)b * TENC + i) * NF2 + HD] = lab[(size_t)b * TENC + i];
    __syncthreads();
    for (int i = tid; i < TENC * NF1; i += 256) {
        int ss = i / NF1, f = i % NF1;
        float a = 0.f;
#pragma unroll 8
        for (int t = 0; t < TENC; t++) a += xs[t * NF1 + f] * ue[ss * TENC + t];
        g_pre1[(size_t)b * TENC * NF1 + i] = a + Ue1b[ss];
    }
}

// ---------------- pre2 (bf16 out) ----------------
__global__ __launch_bounds__(256) void pre2_kernel(
    const float* __restrict__ Ue2, const float* __restrict__ Ue2b) {
    __shared__ float ms[TENC * NF2];
    __shared__ float ue[TENC * TENC];
    int b = blockIdx.x, tid = threadIdx.x;
    for (int i = tid; i < TENC * NF2; i += 256) ms[i] = g_mid[(size_t)b * TENC * NF2 + i];
    for (int i = tid; i < TENC * TENC; i += 256) ue[i] = Ue2[i];
    __syncthreads();
    for (int i = tid; i < TENC * NF2; i += 256) {
        int ss = i / NF2, f = i % NF2;
        float a = 0.f;
#pragma unroll 8
        for (int t = 0; t < TENC; t++) a += ms[t * NF2 + f] * ue[ss * TENC + t];
        g_pre2h[(size_t)b * TENC * NF2 + i] = __float2bfloat16(a + Ue2b[ss]);
    }
}

// ---------------- ud (bf16 out, transposed) ----------------
__global__ __launch_bounds__(256) void ud_kernel(const float* __restrict__ Udb) {
    extern __shared__ float sm_ud[];
    float* udt = sm_ud;
    float* fs  = sm_ud + 16384;
    int b = blockIdx.x, tid = threadIdx.x;
    for (int i = tid; i < HD * HD; i += 256) udt[i] = g_Udt[i];
    for (int i = tid; i < TENC * HD; i += 256) {
        int t = i >> 7, k = i & 127;
        fs[t * 129 + k] = g_fin[(size_t)b * TENC * HD + i];
    }
    __syncthreads();
    for (int u = tid; u < 32 * TENC; u += 256) {
        int t = u % TENC, jq = u / TENC;
        int j0 = 4 * jq;
        float a0 = Udb[j0], a1 = Udb[j0 + 1], a2 = Udb[j0 + 2], a3 = Udb[j0 + 3];
#pragma unroll 8
        for (int k = 0; k < HD; k++) {
            float f = fs[t * 129 + k];
            float4 uu = *(const float4*)(udt + k * HD + j0);
            a0 += f * uu.x; a1 += f * uu.y; a2 += f * uu.z; a3 += f * uu.w;
        }
        size_t base = (size_t)b * HD * TENC;
        g_udTh[base + (size_t)(j0 + 0) * TENC + t] = __float2bfloat16(a0);
        g_udTh[base + (size_t)(j0 + 1) * TENC + t] = __float2bfloat16(a1);
        g_udTh[base + (size_t)(j0 + 2) * TENC + t] = __float2bfloat16(a2);
        g_udTh[base + (size_t)(j0 + 3) * TENC + t] = __float2bfloat16(a3);
    }
}

// ---------------- encoder stage (templated) ----------------
template <int K, int KP, int NF, bool PB16>
__global__ __launch_bounds__(NTH, 1) void stage_kernel(
    const float* __restrict__ inp,
    const float* __restrict__ Ve, const float* __restrict__ Veb,
    const float* __restrict__ WtT, const float* __restrict__ bsum,
    const float* __restrict__ Wet, const float* __restrict__ preF,
    float* __restrict__ outb, int ostride) {
    extern __shared__ float sm[];
    constexpr int PRE_FL = PB16 ? (G * TENC * NF / 2) : (G * TENC * NF);
    constexpr int XS_FL  = PB16 ? 0 : (G * TENC * NF1);
    constexpr int O_PRE = 12288;
    constexpr int O_XS  = O_PRE + PRE_FL;
    constexpr int O_HC  = O_XS + XS_FL;
    constexpr int O_HCT = O_HC + 2048;
    constexpr int O_WE  = O_HCT + 256 * HCT_STR;
    constexpr int O_SC  = O_WE + 384;
    constexpr int O_AL  = O_SC + 1056;
    constexpr int O_IP  = O_AL + 1056;
    constexpr int O_GT  = O_IP + KP * 8;
    constexpr int O_PG  = O_GT + 4096;
    constexpr int O_BS  = O_PG + 4608;
    constexpr int O_VV  = O_BS + 512;

    float* wet    = sm;
    float* pres   = sm + O_PRE;
    float* xs     = sm + O_XS;
    float* hc     = sm + O_HC;
    float* hcT    = sm + O_HCT;
    float* we     = sm + O_WE;
    float* score  = sm + O_SC;
    float* alpha  = sm + O_AL;
    float* inpair = sm + O_IP;
    float* gates  = sm + O_GT;
    float* pg     = sm + O_PG;
    float* bias   = sm + O_BS;
    float* vvec   = sm + O_VV;

    const int tid = threadIdx.x, bid = blockIdx.x;
    const int wid = tid >> 5, lane = tid & 31;

    for (int i = tid; i < 256 * TENC; i += NTH) wet[i] = Wet[i];
    // pre tile
    if (PB16) {
        const unsigned* src = (const unsigned*)(g_pre2h + (size_t)bid * G * TENC * NF2);
        unsigned* dst = (unsigned*)pres;
        for (int i = tid; i < G * TENC * NF2 / 2; i += NTH) dst[i] = src[i];
    } else {
        const float* src = preF + (size_t)bid * G * TENC * NF;
        for (int i = tid; i < G * TENC * NF; i += NTH) pres[i] = src[i];
        // x tile
        for (int i = tid; i < G * TENC * NF1; i += NTH) {
            int g = i / (TENC * NF1);
            int r = i - g * TENC * NF1;
            int t = r / NF1, f = r - t * NF1;
            xs[i] = inp[((size_t)(bid * G + g) * TENC + t) * 18 + f + 1];
        }
    }
    for (int i = tid; i < G * 256; i += NTH) hc[i] = 0.f;
    for (int i = tid; i < 256 * HCT_STR; i += NTH) hcT[i] = 0.f;
    for (int i = tid; i < NG; i += NTH) bias[i] = bsum[i];
    for (int i = tid; i < TENC; i += NTH) vvec[i] = Ve[i];
    if (tid == 0) vvec[130] = Veb[0];
    // zero inpair padding
    for (int i = K * G + tid; i < KP * G; i += NTH) inpair[i] = 0.f;
    __syncthreads();

    const int NITEM = G * NF;
    int i0 = tid, i1 = tid + NTH, i2 = tid + 2 * NTH;
    bool v0 = i0 < NITEM, v1 = i1 < NITEM, v2 = i2 < NITEM;
    int g0 = v0 ? i0 / NF : 0, f0 = v0 ? i0 % NF : 0;
    int g1 = v1 ? i1 / NF : 0, f1 = v1 ? i1 % NF : 0;
    int g2 = v2 ? i2 / NF : 0, f2 = v2 ? i2 % NF : 0;

    for (int t = 0; t < TENC; t++) {
        // A: we projection
        if (tid < 4 * TENC) {
            int p = tid / TENC, ss = tid - p * TENC;
            u64 acc = 0ull;
#pragma unroll 8
            for (int k = 0; k < 256; k++) {
                u64 h2 = *(const u64*)(hcT + k * HCT_STR + 2 * p);
                acc = fma2(dup2(wet[k * TENC + ss]), h2, acc);
            }
            float2 v = unpack2(acc);
            we[(2 * p) * TENC + ss] = v.x;
            we[(2 * p + 1) * TENC + ss] = v.y;
        }
        __syncthreads();
        // B: scores from smem
        {
            float a0 = 0.f, a1 = 0.f, a2 = 0.f;
            if (PB16) {
                const __nv_bfloat16* ph = (const __nv_bfloat16*)pres;
                const __nv_bfloat16* p0 = ph + g0 * TENC * NF + f0;
                const __nv_bfloat16* p1 = ph + g1 * TENC * NF + f1;
                const __nv_bfloat16* p2 = ph + g2 * TENC * NF + f2;
#pragma unroll 4
                for (int ss = 0; ss < TENC; ss++) {
                    float vv = vvec[ss];
                    if (v0) a0 += tanha(we[g0 * TENC + ss] + __bfloat162float(p0[ss * NF])) * vv;
                    if (v1) a1 += tanha(we[g1 * TENC + ss] + __bfloat162float(p1[ss * NF])) * vv;
                    if (v2) a2 += tanha(we[g2 * TENC + ss] + __bfloat162float(p2[ss * NF])) * vv;
                }
            } else {
                const float* p0 = pres + g0 * TENC * NF + f0;
                const float* p1 = pres + g1 * TENC * NF + f1;
                const float* p2 = pres + g2 * TENC * NF + f2;
#pragma unroll 4
                for (int ss = 0; ss < TENC; ss++) {
                    float vv = vvec[ss];
                    if (v0) a0 += tanha(we[g0 * TENC + ss] + p0[ss * NF]) * vv;
                    if (v1) a1 += tanha(we[g1 * TENC + ss] + p1[ss * NF]) * vv;
                    if (v2) a2 += tanha(we[g2 * TENC + ss] + p2[ss * NF]) * vv;
                }
            }
            float bb = vvec[130];
            if (v0) score[g0 * 132 + f0] = a0 + bb;
            if (v1) score[g1 * 132 + f1] = a1 + bb;
            if (v2) score[g2 * 132 + f2] = a2 + bb;
        }
        __syncthreads();
        if (wid < G) warp_softmax(score + wid * 132, alpha + wid * 132, NF, lane);
        __syncthreads();
        // D: gate inputs [x_t*alpha | h]
        for (int idx = tid; idx < K * G; idx += NTH) {
            int k = idx >> 3, g = idx & 7;
            float v;
            if (k < NF) {
                float xv;
                if (PB16) xv = g_mid[((size_t)(bid * G + g) * TENC + t) * NF2 + k];
                else      xv = xs[g * TENC * NF1 + t * NF1 + k];
                v = xv * alpha[g * 132 + k];
            } else {
                v = hc[g * 256 + (k - NF)];
            }
            inpair[k * G + g] = v;
        }
        __syncthreads();
        gates_gemm2<KP>(WtT, bias, inpair, gates, pg, tid);
        __syncthreads();
        // F: cell update + output
        for (int idx = tid; idx < G * HD; idx += NTH) {
            int g = idx >> 7, j = idx & 127;
            float gi = gates[g * NG + j];
            float gf = gates[g * NG + HD + j];
            float gg = gates[g * NG + 2 * HD + j];
            float go = gates[g * NG + 3 * HD + j];
            float c  = hc[g * 256 + HD + j];
            float c2 = siga(gf) * c + siga(gi) * tanha(gg);
            float h  = siga(go) * tanha(c2);
            hc[g * 256 + j] = h;
            hc[g * 256 + HD + j] = c2;
            hcT[j * HCT_STR + g] = h;
            hcT[(128 + j) * HCT_STR + g] = c2;
            outb[((size_t)(bid * G + g) * TENC + t) * ostride + j] = h;
        }
        __syncthreads();
    }
}

// ---------------- decoder ----------------
#define D_O_WDT 0
#define D_O_HC  32768
#define D_O_HCT 34816
#define D_O_WD  37376
#define D_O_SC  38400
#define D_O_AL  38784
#define D_O_IP  39168
#define D_O_GT  41216
#define D_O_PG  45312
#define D_O_BS  49920
#define D_O_VV  50432
#define D_O_VR  50568
#define DEC_SMEM_FL 50704

__global__ __launch_bounds__(NTH, 1) void decoder_kernel(
    const float* __restrict__ Vd, const float* __restrict__ Vdb,
    const float* __restrict__ regW, const float* __restrict__ regb,
    float* __restrict__ out) {
    extern __shared__ float sm[];
    float* wdt    = sm + D_O_WDT;
    float* hc     = sm + D_O_HC;
    float* hcT    = sm + D_O_HCT;
    float* wd     = sm + D_O_WD;
    float* score  = sm + D_O_SC;
    float* alpha  = sm + D_O_AL;
    float* inpair = sm + D_O_IP;
    float* gates  = sm + D_O_GT;
    float* pg     = sm + D_O_PG;
    float* bias   = sm + D_O_BS;
    float* vvec   = sm + D_O_VV;
    float* vreg   = sm + D_O_VR;

    const int tid = threadIdx.x, bid = blockIdx.x;
    const int wid = tid >> 5, lane = tid & 31;

    for (int i = tid; i < 256 * HD; i += NTH) wdt[i] = g_Wdt[i];
    for (int i = tid; i < G * 256; i += NTH) hc[i] = 0.f;
    for (int i = tid; i < 256 * HCT_STR; i += NTH) hcT[i] = 0.f;
    for (int i = tid; i < NG; i += NTH) bias[i] = g_bd[i];
    for (int i = tid; i < HD; i += NTH) { vvec[i] = Vd[i]; vreg[i] = regW[i]; }
    if (tid == 0) { vvec[130] = Vdb[0]; vreg[130] = regb[0]; }
    __syncthreads();

    // score mapping: 384 threads, one (g,t) each
    bool sval = tid < G * TENC;
    int sg = sval ? tid / TENC : 0, stt = sval ? tid % TENC : 0;
    const __nv_bfloat16* up = g_udTh + ((size_t)(bid * G + sg) * HD) * TENC + stt;
    // din mapping: (g, j pair)
    int dg = tid >> 6, dj = (tid & 63) * 2;
    const float* fp = g_fin + ((size_t)(bid * G + dg) * TENC) * HD + dj;

    for (int sd = 0; sd < DSTEPS; sd++) {
        // A: wd projection (all 512 threads)
        {
            int p = tid >> 7, j = tid & 127;
            u64 acc = 0ull;
#pragma unroll 8
            for (int k = 0; k < 256; k++) {
                u64 h2 = *(const u64*)(hcT + k * HCT_STR + 2 * p);
                acc = fma2(dup2(wdt[k * HD + j]), h2, acc);
            }
            float2 v = unpack2(acc);
            wd[(2 * p) * HD + j] = v.x;
            wd[(2 * p + 1) * HD + j] = v.y;
        }
        __syncthreads();
        // B: score from global bf16 udT (coalesced) + smem wd
        {
            float a = 0.f;
#pragma unroll 4
            for (int j = 0; j < HD; j++)
                a += tanha(wd[sg * HD + j] + __bfloat162float(up[(size_t)j * TENC])) * vvec[j];
            if (sval) score[sg * TENC + stt] = a + vvec[130];
        }
        __syncthreads();
        if (wid < G) warp_softmax(score + wid * TENC, alpha + wid * TENC, TENC, lane);
        __syncthreads();
        // D: din + inpair (2 j per thread)
        {
            float a0 = 0.f, a1 = 0.f;
#pragma unroll 4
            for (int tt = 0; tt < TENC; tt++) {
                float al = alpha[dg * TENC + tt];
                float2 f2 = *(const float2*)(fp + (size_t)tt * HD);
                a0 += al * f2.x; a1 += al * f2.y;
            }
            inpair[dj * G + dg] = a0;
            inpair[(dj + 1) * G + dg] = a1;
            inpair[(HD + dj) * G + dg] = hc[dg * 256 + dj];
            inpair[(HD + dj + 1) * G + dg] = hc[dg * 256 + dj + 1];
        }
        __syncthreads();
        gates_gemm2<KPD>(g_WtTd, bias, inpair, gates, pg, tid);
        __syncthreads();
        // F: cell
        for (int idx = tid; idx < G * HD; idx += NTH) {
            int g = idx >> 7, j = idx & 127;
            float gi = gates[g * NG + j];
            float gf = gates[g * NG + HD + j];
            float gg = gates[g * NG + 2 * HD + j];
            float go = gates[g * NG + 3 * HD + j];
            float c  = hc[g * 256 + HD + j];
            float c2 = siga(gf) * c + siga(gi) * tanha(gg);
            float h  = siga(go) * tanha(c2);
            hc[g * 256 + j] = h;
            hc[g * 256 + HD + j] = c2;
            hcT[j * HCT_STR + g] = h;
            hcT[(128 + j) * HCT_STR + g] = c2;
        }
        __syncthreads();
        if (sd >= DSTEPS - TDEC && wid < G) {
            float a = 0.f;
#pragma unroll
            for (int r = 0; r < 4; r++)
                a += hc[wid * 256 + lane + 32 * r] * vreg[lane + 32 * r];
#pragma unroll
            for (int o = 16; o; o >>= 1) a += __shfl_xor_sync(0xffffffffu, a, o);
            if (lane == 0)
                out[(size_t)(bid * G + wid) * TDEC + (sd - (DSTEPS - TDEC))] = a + vreg[130];
        }
    }
}

// ---------------- launch ----------------
extern "C" void kernel_launch(void* const* d_in, const int* in_sizes, int n_in,
                              void* d_out, int out_size) {
    const float* input_p_q = (const float*)d_in[0];
    const float* label_p   = (const float*)d_in[1];
    const float* Ue1_W = (const float*)d_in[2];
    const float* Ue1_b = (const float*)d_in[3];
    const float* We1_W = (const float*)d_in[4];
    const float* Ve1_W = (const float*)d_in[5];
    const float* Ve1_b = (const float*)d_in[6];
    const float* Ue2_W = (const float*)d_in[7];
    const float* Ue2_b = (const float*)d_in[8];
    const float* We2_W = (const float*)d_in[9];
    const float* Ve2_W = (const float*)d_in[10];
    const float* Ve2_b = (const float*)d_in[11];
    const float* Ud_W  = (const float*)d_in[12];
    const float* Ud_b  = (const float*)d_in[13];
    const float* Wd_W  = (const float*)d_in[14];
    const float* Vd_W  = (const float*)d_in[15];
    const float* Vd_b  = (const float*)d_in[16];
    const float* e1_Wih = (const float*)d_in[17];
    const float* e1_Whh = (const float*)d_in[18];
    const float* e1_bih = (const float*)d_in[19];
    const float* e1_bhh = (const float*)d_in[20];
    const float* e2_Wih = (const float*)d_in[21];
    const float* e2_Whh = (const float*)d_in[22];
    const float* e2_bih = (const float*)d_in[23];
    const float* e2_bhh = (const float*)d_in[24];
    const float* d_Wih  = (const float*)d_in[25];
    const float* d_Whh  = (const float*)d_in[26];
    const float* d_bih  = (const float*)d_in[27];
    const float* d_bhh  = (const float*)d_in[28];
    const float* reg_W  = (const float*)d_in[29];
    const float* reg_b  = (const float*)d_in[30];
    float* out = (float*)d_out;

    float *p_WtT1, *p_WtT2, *p_Wet1, *p_Wet2;
    float *p_b1, *p_b2, *p_pre1, *p_mid, *p_fin;
    cudaGetSymbolAddress((void**)&p_WtT1, g_WtT1);
    cudaGetSymbolAddress((void**)&p_WtT2, g_WtT2);
    cudaGetSymbolAddress((void**)&p_Wet1, g_Wet1);
    cudaGetSymbolAddress((void**)&p_Wet2, g_Wet2);
    cudaGetSymbolAddress((void**)&p_b1, g_b1);
    cudaGetSymbolAddress((void**)&p_b2, g_b2);
    cudaGetSymbolAddress((void**)&p_pre1, g_pre1);
    cudaGetSymbolAddress((void**)&p_mid, g_mid);
    cudaGetSymbolAddress((void**)&p_fin, g_fin);

    const int STAGE1_SMEM = 43016 * 4;
    const int STAGE2_SMEM = 55624 * 4;
    const int DEC_SMEM    = DEC_SMEM_FL * 4;
    const int UD_SMEM     = (16384 + TENC * 129) * 4;

    cudaFuncSetAttribute((const void*)stage_kernel<K1, KP1, NF1, false>,
                         cudaFuncAttributeMaxDynamicSharedMemorySize, STAGE1_SMEM);
    cudaFuncSetAttribute((const void*)stage_kernel<K2, KP2, NF2, true>,
                         cudaFuncAttributeMaxDynamicSharedMemorySize, STAGE2_SMEM);
    cudaFuncSetAttribute((const void*)decoder_kernel,
                         cudaFuncAttributeMaxDynamicSharedMemorySize, DEC_SMEM);
    cudaFuncSetAttribute((const void*)ud_kernel,
                         cudaFuncAttributeMaxDynamicSharedMemorySize, UD_SMEM);

    setup_kernel<<<128, 256>>>(e1_Wih, e1_Whh, e2_Wih, e2_Whh, d_Wih, d_Whh,
                               We1_W, We2_W, Wd_W, Ud_W,
                               e1_bih, e1_bhh, e2_bih, e2_bhh, d_bih, d_bhh);
    pre1_kernel<<<BTOT, 256>>>(input_p_q, label_p, Ue1_W, Ue1_b);
    stage_kernel<K1, KP1, NF1, false><<<NCTA, NTH, STAGE1_SMEM>>>(
        input_p_q, Ve1_W, Ve1_b, p_WtT1, p_b1, p_Wet1, p_pre1, p_mid, NF2);
    pre2_kernel<<<BTOT, 256>>>(Ue2_W, Ue2_b);
    stage_kernel<K2, KP2, NF2, true><<<NCTA, NTH, STAGE2_SMEM>>>(
        input_p_q, Ve2_W, Ve2_b, p_WtT2, p_b2, p_Wet2, nullptr, p_fin, HD);
    ud_kernel<<<BTOT, 256, UD_SMEM>>>(Ud_b);
    decoder_kernel<<<NCTA, NTH, DEC_SMEM>>>(Vd_W, Vd_b, reg_W, reg_b, out);
}

// round 5
// speedup vs baseline: 1.8246x; 1.8246x over previous
#include <cuda_runtime.h>
#include <cuda_bf16.h>

#define TENC 48
#define TDEC 24
#define DSTEPS 30
#define HD 128
#define NF1 17
#define NF2 129
#define K1 145
#define KP1 152
#define K2 257
#define KP2 264
#define KD 256
#define KPD 256
#define G 8
#define NCTA 128
#define NTH 512
#define NG 512
#define BTOT 1024
#define HCT_STR 10

typedef unsigned long long u64;

// ---------------- device scratch (allocation-free) ----------------
__device__ __nv_bfloat16 g_WtB1[KP1 * NG];    // [k][n] bf16, zero-padded k
__device__ __nv_bfloat16 g_WtB2[KP2 * NG];
__device__ __nv_bfloat16 g_WtBd[KPD * NG];
__device__ float g_Wet1[256 * TENC];
__device__ float g_Wet2[256 * TENC];
__device__ float g_Wdt[256 * HD];             // [k][j]
__device__ float g_Udt[HD * HD];
__device__ float g_b1[NG], g_b2[NG], g_bd[NG];
__device__ float g_pre1[BTOT * TENC * NF1];           // [b][s][f] fp32
__device__ __nv_bfloat16 g_pre2h[BTOT * TENC * NF2];  // [b][s][f] bf16
__device__ float g_mid[BTOT * TENC * NF2];            // [b][t][f] (f=128 label)
__device__ float g_fin[BTOT * TENC * HD];             // [b][t][j]
__device__ __nv_bfloat16 g_udTh[BTOT * HD * TENC];    // [b][j][t] bf16

// ---------------- math helpers ----------------
__device__ __forceinline__ float tanha(float x) {
    float y; asm("tanh.approx.f32 %0, %1;" : "=f"(y) : "f"(x)); return y;
}
__device__ __forceinline__ float siga(float x) {
    return fmaf(tanha(0.5f * x), 0.5f, 0.5f);
}
__device__ __forceinline__ u64 fma2(u64 a, u64 b, u64 c) {
    u64 d; asm("fma.rn.f32x2 %0, %1, %2, %3;" : "=l"(d) : "l"(a), "l"(b), "l"(c)); return d;
}
__device__ __forceinline__ u64 dup2(float x) {
    u64 d; unsigned r = __float_as_uint(x);
    asm("mov.b64 %0, {%1, %1};" : "=l"(d) : "r"(r)); return d;
}
__device__ __forceinline__ float2 unpack2(u64 a) {
    unsigned l, h;
    asm("mov.b64 {%0, %1}, %2;" : "=r"(l), "=r"(h) : "l"(a));
    return make_float2(__uint_as_float(l), __uint_as_float(h));
}

__device__ __forceinline__ void warp_softmax(const float* score_row, float* alpha_row,
                                             int F, int lane) {
    float mx = -1e30f;
    for (int f = lane; f < F; f += 32) mx = fmaxf(mx, score_row[f]);
#pragma unroll
    for (int o = 16; o; o >>= 1) mx = fmaxf(mx, __shfl_xor_sync(0xffffffffu, mx, o));
    float sm = 0.f;
    for (int f = lane; f < F; f += 32) {
        float e = __expf(score_row[f] - mx);
        alpha_row[f] = e;
        sm += e;
    }
#pragma unroll
    for (int o = 16; o; o >>= 1) sm += __shfl_xor_sync(0xffffffffu, sm, o);
    float inv = __fdividef(1.f, sm);
    for (int f = lane; f < F; f += 32) alpha_row[f] *= inv;
}

// gate GEMM: [k][n]-major bf16 weights (coalesced), K split across thread halves.
// inpair smem [KP][8], gates smem [8][NG], pg smem [NG][9] partials, bias smem [NG].
template <int KP>
__device__ __forceinline__ void gates_gemm3(const __nv_bfloat16* __restrict__ WtB,
                                            const float* __restrict__ bias,
                                            const float* __restrict__ inpair,
                                            float* __restrict__ gates,
                                            float* __restrict__ pg, int tid) {
    const int half = tid >> 8;
    const int lt = tid & 255;
    const int n0 = lt * 2;
    constexpr int KH = KP / 2;
    const int k0 = half * KH;
    u64 a0 = 0, a1 = 0, a2 = 0, a3 = 0, a4 = 0, a5 = 0, a6 = 0, a7 = 0;
    const __nv_bfloat162* wp =
        (const __nv_bfloat162*)(WtB + (size_t)k0 * NG + n0);
    const float* ipp = inpair + k0 * G;
#pragma unroll 4
    for (int k = 0; k < KH; k++) {
        float2 wf = __bfloat1622float2(wp[(size_t)k * (NG / 2)]);
        u64 w0 = dup2(wf.x), w1 = dup2(wf.y);
        ulonglong2 iab = *(const ulonglong2*)(ipp + k * G);
        ulonglong2 icd = *(const ulonglong2*)(ipp + k * G + 4);
        a0 = fma2(w0, iab.x, a0); a1 = fma2(w0, iab.y, a1);
        a2 = fma2(w0, icd.x, a2); a3 = fma2(w0, icd.y, a3);
        a4 = fma2(w1, iab.x, a4); a5 = fma2(w1, iab.y, a5);
        a6 = fma2(w1, icd.x, a6); a7 = fma2(w1, icd.y, a7);
    }
    if (half) {
        float* pp = pg + n0 * 9;
        float2 r;
        r = unpack2(a0); pp[0] = r.x; pp[1] = r.y;
        r = unpack2(a1); pp[2] = r.x; pp[3] = r.y;
        r = unpack2(a2); pp[4] = r.x; pp[5] = r.y;
        r = unpack2(a3); pp[6] = r.x; pp[7] = r.y;
        pp += 9;
        r = unpack2(a4); pp[0] = r.x; pp[1] = r.y;
        r = unpack2(a5); pp[2] = r.x; pp[3] = r.y;
        r = unpack2(a6); pp[4] = r.x; pp[5] = r.y;
        r = unpack2(a7); pp[6] = r.x; pp[7] = r.y;
    }
    __syncthreads();
    if (!half) {
        const float* pp = pg + n0 * 9;
        const float* pq = pp + 9;
        float b0 = bias[n0], b1 = bias[n0 + 1];
        float2 r;
        r = unpack2(a0); gates[0*NG+n0] = r.x + pp[0] + b0; gates[1*NG+n0] = r.y + pp[1] + b0;
        r = unpack2(a1); gates[2*NG+n0] = r.x + pp[2] + b0; gates[3*NG+n0] = r.y + pp[3] + b0;
        r = unpack2(a2); gates[4*NG+n0] = r.x + pp[4] + b0; gates[5*NG+n0] = r.y + pp[5] + b0;
        r = unpack2(a3); gates[6*NG+n0] = r.x + pp[6] + b0; gates[7*NG+n0] = r.y + pp[7] + b0;
        r = unpack2(a4); gates[0*NG+n0+1] = r.x + pq[0] + b1; gates[1*NG+n0+1] = r.y + pq[1] + b1;
        r = unpack2(a5); gates[2*NG+n0+1] = r.x + pq[2] + b1; gates[3*NG+n0+1] = r.y + pq[3] + b1;
        r = unpack2(a6); gates[4*NG+n0+1] = r.x + pq[4] + b1; gates[5*NG+n0+1] = r.y + pq[5] + b1;
        r = unpack2(a7); gates[6*NG+n0+1] = r.x + pq[6] + b1; gates[7*NG+n0+1] = r.y + pq[7] + b1;
    }
}

// ---------------- setup ----------------
__global__ void setup_kernel(
    const float* __restrict__ e1_Wih, const float* __restrict__ e1_Whh,
    const float* __restrict__ e2_Wih, const float* __restrict__ e2_Whh,
    const float* __restrict__ d_Wih,  const float* __restrict__ d_Whh,
    const float* __restrict__ We1,    const float* __restrict__ We2,
    const float* __restrict__ Wd,     const float* __restrict__ Ud,
    const float* __restrict__ e1_bih, const float* __restrict__ e1_bhh,
    const float* __restrict__ e2_bih, const float* __restrict__ e2_bhh,
    const float* __restrict__ d_bih,  const float* __restrict__ d_bhh) {
    int tid = blockIdx.x * blockDim.x + threadIdx.x;
    int nt = gridDim.x * blockDim.x;
    for (int i = tid; i < KP1 * NG; i += nt) {
        int k = i / NG, n = i % NG;
        float v = 0.f;
        if (k < K1) v = (k < NF1) ? e1_Wih[n * NF1 + k] : e1_Whh[n * HD + (k - NF1)];
        g_WtB1[i] = __float2bfloat16(v);
    }
    for (int i = tid; i < KP2 * NG; i += nt) {
        int k = i / NG, n = i % NG;
        float v = 0.f;
        if (k < K2) v = (k < NF2) ? e2_Wih[n * NF2 + k] : e2_Whh[n * HD + (k - NF2)];
        g_WtB2[i] = __float2bfloat16(v);
    }
    for (int i = tid; i < KPD * NG; i += nt) {
        int k = i / NG, n = i % NG;
        float v = (k < HD) ? d_Wih[n * HD + k] : d_Whh[n * HD + (k - HD)];
        g_WtBd[i] = __float2bfloat16(v);
    }
    for (int i = tid; i < 256 * TENC; i += nt) {
        int k = i / TENC, ss = i % TENC;
        g_Wet1[i] = We1[ss * 256 + k];
        g_Wet2[i] = We2[ss * 256 + k];
    }
    for (int i = tid; i < 256 * HD; i += nt) {
        int k = i / HD, j = i % HD;
        g_Wdt[i] = Wd[j * 256 + k];
    }
    for (int i = tid; i < HD * HD; i += nt) {
        int k = i / HD, j = i % HD;
        g_Udt[i] = Ud[j * HD + k];
    }
    for (int i = tid; i < NG; i += nt) {
        g_b1[i] = e1_bih[i] + e1_bhh[i];
        g_b2[i] = e2_bih[i] + e2_bhh[i];
        g_bd[i] = d_bih[i] + d_bhh[i];
    }
}

// ---------------- pre1 ----------------
__global__ __launch_bounds__(256) void pre1_kernel(
    const float* __restrict__ inp, const float* __restrict__ lab,
    const float* __restrict__ Ue1, const float* __restrict__ Ue1b) {
    __shared__ float xs[TENC * NF1];
    __shared__ float ue[TENC * TENC];
    int b = blockIdx.x, tid = threadIdx.x;
    for (int i = tid; i < TENC * NF1; i += 256) {
        int t = i / NF1, f = i % NF1;
        xs[i] = inp[((size_t)b * TENC + t) * 18 + f + 1];
    }
    for (int i = tid; i < TENC * TENC; i += 256) ue[i] = Ue1[i];
    for (int i = tid; i < TENC; i += 256)
        g_mid[((size_t)b * TENC + i) * NF2 + HD] = lab[(size_t)b * TENC + i];
    __syncthreads();
    for (int i = tid; i < TENC * NF1; i += 256) {
        int ss = i / NF1, f = i % NF1;
        float a = 0.f;
#pragma unroll 8
        for (int t = 0; t < TENC; t++) a += xs[t * NF1 + f] * ue[ss * TENC + t];
        g_pre1[(size_t)b * TENC * NF1 + i] = a + Ue1b[ss];
    }
}

// ---------------- pre2 (bf16 out) ----------------
__global__ __launch_bounds__(256) void pre2_kernel(
    const float* __restrict__ Ue2, const float* __restrict__ Ue2b) {
    __shared__ float ms[TENC * NF2];
    __shared__ float ue[TENC * TENC];
    int b = blockIdx.x, tid = threadIdx.x;
    for (int i = tid; i < TENC * NF2; i += 256) ms[i] = g_mid[(size_t)b * TENC * NF2 + i];
    for (int i = tid; i < TENC * TENC; i += 256) ue[i] = Ue2[i];
    __syncthreads();
    for (int i = tid; i < TENC * NF2; i += 256) {
        int ss = i / NF2, f = i % NF2;
        float a = 0.f;
#pragma unroll 8
        for (int t = 0; t < TENC; t++) a += ms[t * NF2 + f] * ue[ss * TENC + t];
        g_pre2h[(size_t)b * TENC * NF2 + i] = __float2bfloat16(a + Ue2b[ss]);
    }
}

// ---------------- ud (bf16 out, transposed) ----------------
__global__ __launch_bounds__(256) void ud_kernel(const float* __restrict__ Udb) {
    extern __shared__ float sm_ud[];
    float* udt = sm_ud;
    float* fs  = sm_ud + 16384;
    int b = blockIdx.x, tid = threadIdx.x;
    for (int i = tid; i < HD * HD; i += 256) udt[i] = g_Udt[i];
    for (int i = tid; i < TENC * HD; i += 256) {
        int t = i >> 7, k = i & 127;
        fs[t * 129 + k] = g_fin[(size_t)b * TENC * HD + i];
    }
    __syncthreads();
    for (int u = tid; u < 32 * TENC; u += 256) {
        int t = u % TENC, jq = u / TENC;
        int j0 = 4 * jq;
        float a0 = Udb[j0], a1 = Udb[j0 + 1], a2 = Udb[j0 + 2], a3 = Udb[j0 + 3];
#pragma unroll 8
        for (int k = 0; k < HD; k++) {
            float f = fs[t * 129 + k];
            float4 uu = *(const float4*)(udt + k * HD + j0);
            a0 += f * uu.x; a1 += f * uu.y; a2 += f * uu.z; a3 += f * uu.w;
        }
        size_t base = (size_t)b * HD * TENC;
        g_udTh[base + (size_t)(j0 + 0) * TENC + t] = __float2bfloat16(a0);
        g_udTh[base + (size_t)(j0 + 1) * TENC + t] = __float2bfloat16(a1);
        g_udTh[base + (size_t)(j0 + 2) * TENC + t] = __float2bfloat16(a2);
        g_udTh[base + (size_t)(j0 + 3) * TENC + t] = __float2bfloat16(a3);
    }
}

// ---------------- encoder stage (templated) ----------------
template <int K, int KP, int NF, bool PB16>
__global__ __launch_bounds__(NTH, 1) void stage_kernel(
    const float* __restrict__ inp,
    const float* __restrict__ Ve, const float* __restrict__ Veb,
    const __nv_bfloat16* __restrict__ WtB, const float* __restrict__ bsum,
    const float* __restrict__ Wet, const float* __restrict__ preF,
    float* __restrict__ outb, int ostride) {
    extern __shared__ float sm[];
    constexpr int PRE_FL = PB16 ? (G * TENC * NF / 2) : (G * TENC * NF);
    constexpr int XS_FL  = PB16 ? 0 : (G * TENC * NF1);
    constexpr int O_PRE = 12288;
    constexpr int O_XS  = O_PRE + PRE_FL;
    constexpr int O_HC  = O_XS + XS_FL;
    constexpr int O_HCT = O_HC + 2048;
    constexpr int O_WE  = O_HCT + 256 * HCT_STR;
    constexpr int O_SC  = O_WE + 384;
    constexpr int O_AL  = O_SC + 1056;
    constexpr int O_IP  = O_AL + 1056;
    constexpr int O_GT  = O_IP + KP * 8;
    constexpr int O_PG  = O_GT + 4096;
    constexpr int O_BS  = O_PG + 4608;
    constexpr int O_VV  = O_BS + 512;

    float* wet    = sm;
    float* pres   = sm + O_PRE;
    float* xs     = sm + O_XS;
    float* hc     = sm + O_HC;
    float* hcT    = sm + O_HCT;
    float* we     = sm + O_WE;
    float* score  = sm + O_SC;
    float* alpha  = sm + O_AL;
    float* inpair = sm + O_IP;
    float* gates  = sm + O_GT;
    float* pg     = sm + O_PG;
    float* bias   = sm + O_BS;
    float* vvec   = sm + O_VV;

    const int tid = threadIdx.x, bid = blockIdx.x;
    const int wid = tid >> 5, lane = tid & 31;

    for (int i = tid; i < 256 * TENC; i += NTH) wet[i] = Wet[i];
    if (PB16) {
        const unsigned* src = (const unsigned*)(g_pre2h + (size_t)bid * G * TENC * NF2);
        unsigned* dst = (unsigned*)pres;
        for (int i = tid; i < G * TENC * NF2 / 2; i += NTH) dst[i] = src[i];
    } else {
        const float* src = preF + (size_t)bid * G * TENC * NF;
        for (int i = tid; i < G * TENC * NF; i += NTH) pres[i] = src[i];
        for (int i = tid; i < G * TENC * NF1; i += NTH) {
            int g = i / (TENC * NF1);
            int r = i - g * TENC * NF1;
            int t = r / NF1, f = r - t * NF1;
            xs[i] = inp[((size_t)(bid * G + g) * TENC + t) * 18 + f + 1];
        }
    }
    for (int i = tid; i < G * 256; i += NTH) hc[i] = 0.f;
    for (int i = tid; i < 256 * HCT_STR; i += NTH) hcT[i] = 0.f;
    for (int i = tid; i < NG; i += NTH) bias[i] = bsum[i];
    for (int i = tid; i < TENC; i += NTH) vvec[i] = Ve[i];
    if (tid == 0) vvec[130] = Veb[0];
    for (int i = K * G + tid; i < KP * G; i += NTH) inpair[i] = 0.f;
    __syncthreads();

    const int NITEM = G * NF;
    int i0 = tid, i1 = tid + NTH, i2 = tid + 2 * NTH;
    bool v0 = i0 < NITEM, v1 = i1 < NITEM, v2 = i2 < NITEM;
    int g0 = v0 ? i0 / NF : 0, f0 = v0 ? i0 % NF : 0;
    int g1 = v1 ? i1 / NF : 0, f1 = v1 ? i1 % NF : 0;
    int g2 = v2 ? i2 / NF : 0, f2 = v2 ? i2 % NF : 0;

    for (int t = 0; t < TENC; t++) {
        // A: we projection
        if (tid < 4 * TENC) {
            int p = tid / TENC, ss = tid - p * TENC;
            u64 acc = 0ull;
#pragma unroll 8
            for (int k = 0; k < 256; k++) {
                u64 h2 = *(const u64*)(hcT + k * HCT_STR + 2 * p);
                acc = fma2(dup2(wet[k * TENC + ss]), h2, acc);
            }
            float2 v = unpack2(acc);
            we[(2 * p) * TENC + ss] = v.x;
            we[(2 * p + 1) * TENC + ss] = v.y;
        }
        __syncthreads();
        // B: scores from smem
        {
            float a0 = 0.f, a1 = 0.f, a2 = 0.f;
            if (PB16) {
                const __nv_bfloat16* ph = (const __nv_bfloat16*)pres;
                const __nv_bfloat16* p0 = ph + g0 * TENC * NF + f0;
                const __nv_bfloat16* p1 = ph + g1 * TENC * NF + f1;
                const __nv_bfloat16* p2 = ph + g2 * TENC * NF + f2;
#pragma unroll 4
                for (int ss = 0; ss < TENC; ss++) {
                    float vv = vvec[ss];
                    if (v0) a0 += tanha(we[g0 * TENC + ss] + __bfloat162float(p0[ss * NF])) * vv;
                    if (v1) a1 += tanha(we[g1 * TENC + ss] + __bfloat162float(p1[ss * NF])) * vv;
                    if (v2) a2 += tanha(we[g2 * TENC + ss] + __bfloat162float(p2[ss * NF])) * vv;
                }
            } else {
                const float* p0 = pres + g0 * TENC * NF + f0;
                const float* p1 = pres + g1 * TENC * NF + f1;
                const float* p2 = pres + g2 * TENC * NF + f2;
#pragma unroll 4
                for (int ss = 0; ss < TENC; ss++) {
                    float vv = vvec[ss];
                    if (v0) a0 += tanha(we[g0 * TENC + ss] + p0[ss * NF]) * vv;
                    if (v1) a1 += tanha(we[g1 * TENC + ss] + p1[ss * NF]) * vv;
                    if (v2) a2 += tanha(we[g2 * TENC + ss] + p2[ss * NF]) * vv;
                }
            }
            float bb = vvec[130];
            if (v0) score[g0 * 132 + f0] = a0 + bb;
            if (v1) score[g1 * 132 + f1] = a1 + bb;
            if (v2) score[g2 * 132 + f2] = a2 + bb;
        }
        __syncthreads();
        if (wid < G) warp_softmax(score + wid * 132, alpha + wid * 132, NF, lane);
        __syncthreads();
        // D: gate inputs [x_t*alpha | h]
        for (int idx = tid; idx < K * G; idx += NTH) {
            int k = idx >> 3, g = idx & 7;
            float v;
            if (k < NF) {
                float xv;
                if (PB16) xv = g_mid[((size_t)(bid * G + g) * TENC + t) * NF2 + k];
                else      xv = xs[g * TENC * NF1 + t * NF1 + k];
                v = xv * alpha[g * 132 + k];
            } else {
                v = hc[g * 256 + (k - NF)];
            }
            inpair[k * G + g] = v;
        }
        __syncthreads();
        gates_gemm3<KP>(WtB, bias, inpair, gates, pg, tid);
        __syncthreads();
        // F: cell update + output
        for (int idx = tid; idx < G * HD; idx += NTH) {
            int g = idx >> 7, j = idx & 127;
            float gi = gates[g * NG + j];
            float gf = gates[g * NG + HD + j];
            float gg = gates[g * NG + 2 * HD + j];
            float go = gates[g * NG + 3 * HD + j];
            float c  = hc[g * 256 + HD + j];
            float c2 = siga(gf) * c + siga(gi) * tanha(gg);
            float h  = siga(go) * tanha(c2);
            hc[g * 256 + j] = h;
            hc[g * 256 + HD + j] = c2;
            hcT[j * HCT_STR + g] = h;
            hcT[(128 + j) * HCT_STR + g] = c2;
            outb[((size_t)(bid * G + g) * TENC + t) * ostride + j] = h;
        }
        __syncthreads();
    }
}

// ---------------- decoder ----------------
#define D_O_WDT 0
#define D_O_HC  32768
#define D_O_HCT 34816
#define D_O_WD  37376
#define D_O_SC  38400
#define D_O_AL  38784
#define D_O_IP  39168
#define D_O_GT  41216
#define D_O_PG  45312
#define D_O_BS  49920
#define D_O_VV  50432
#define D_O_VR  50568
#define DEC_SMEM_FL 50704

__global__ __launch_bounds__(NTH, 1) void decoder_kernel(
    const float* __restrict__ Vd, const float* __restrict__ Vdb,
    const float* __restrict__ regW, const float* __restrict__ regb,
    float* __restrict__ out) {
    extern __shared__ float sm[];
    float* wdt    = sm + D_O_WDT;
    float* hc     = sm + D_O_HC;
    float* hcT    = sm + D_O_HCT;
    float* wd     = sm + D_O_WD;
    float* score  = sm + D_O_SC;
    float* alpha  = sm + D_O_AL;
    float* inpair = sm + D_O_IP;
    float* gates  = sm + D_O_GT;
    float* pg     = sm + D_O_PG;
    float* bias   = sm + D_O_BS;
    float* vvec   = sm + D_O_VV;
    float* vreg   = sm + D_O_VR;

    const int tid = threadIdx.x, bid = blockIdx.x;
    const int wid = tid >> 5, lane = tid & 31;

    for (int i = tid; i < 256 * HD; i += NTH) wdt[i] = g_Wdt[i];
    for (int i = tid; i < G * 256; i += NTH) hc[i] = 0.f;
    for (int i = tid; i < 256 * HCT_STR; i += NTH) hcT[i] = 0.f;
    for (int i = tid; i < NG; i += NTH) bias[i] = g_bd[i];
    for (int i = tid; i < HD; i += NTH) { vvec[i] = Vd[i]; vreg[i] = regW[i]; }
    if (tid == 0) { vvec[130] = Vdb[0]; vreg[130] = regb[0]; }
    __syncthreads();

    bool sval = tid < G * TENC;
    int sg = sval ? tid / TENC : 0, stt = sval ? tid % TENC : 0;
    const __nv_bfloat16* up = g_udTh + ((size_t)(bid * G + sg) * HD) * TENC + stt;
    int dg = tid >> 6, dj = (tid & 63) * 2;
    const float* fp = g_fin + ((size_t)(bid * G + dg) * TENC) * HD + dj;

    for (int sd = 0; sd < DSTEPS; sd++) {
        // A: wd projection (all 512 threads)
        {
            int p = tid >> 7, j = tid & 127;
            u64 acc = 0ull;
#pragma unroll 8
            for (int k = 0; k < 256; k++) {
                u64 h2 = *(const u64*)(hcT + k * HCT_STR + 2 * p);
                acc = fma2(dup2(wdt[k * HD + j]), h2, acc);
            }
            float2 v = unpack2(acc);
            wd[(2 * p) * HD + j] = v.x;
            wd[(2 * p + 1) * HD + j] = v.y;
        }
        __syncthreads();
        // B: score from global bf16 udT (coalesced) + smem wd
        {
            float a = 0.f;
#pragma unroll 4
            for (int j = 0; j < HD; j++)
                a += tanha(wd[sg * HD + j] + __bfloat162float(up[(size_t)j * TENC])) * vvec[j];
            if (sval) score[sg * TENC + stt] = a + vvec[130];
        }
        __syncthreads();
        if (wid < G) warp_softmax(score + wid * TENC, alpha + wid * TENC, TENC, lane);
        __syncthreads();
        // D: din + inpair (2 j per thread)
        {
            float a0 = 0.f, a1 = 0.f;
#pragma unroll 4
            for (int tt = 0; tt < TENC; tt++) {
                float al = alpha[dg * TENC + tt];
                float2 f2 = *(const float2*)(fp + (size_t)tt * HD);
                a0 += al * f2.x; a1 += al * f2.y;
            }
            inpair[dj * G + dg] = a0;
            inpair[(dj + 1) * G + dg] = a1;
            inpair[(HD + dj) * G + dg] = hc[dg * 256 + dj];
            inpair[(HD + dj + 1) * G + dg] = hc[dg * 256 + dj + 1];
        }
        __syncthreads();
        gates_gemm3<KPD>(g_WtBd, bias, inpair, gates, pg, tid);
        __syncthreads();
        // F: cell
        for (int idx = tid; idx < G * HD; idx += NTH) {
            int g = idx >> 7, j = idx & 127;
            float gi = gates[g * NG + j];
            float gf = gates[g * NG + HD + j];
            float gg = gates[g * NG + 2 * HD + j];
            float go = gates[g * NG + 3 * HD + j];
            float c  = hc[g * 256 + HD + j];
            float c2 = siga(gf) * c + siga(gi) * tanha(gg);
            float h  = siga(go) * tanha(c2);
            hc[g * 256 + j] = h;
            hc[g * 256 + HD + j] = c2;
            hcT[j * HCT_STR + g] = h;
            hcT[(128 + j) * HCT_STR + g] = c2;
        }
        __syncthreads();
        if (sd >= DSTEPS - TDEC && wid < G) {
            float a = 0.f;
#pragma unroll
            for (int r = 0; r < 4; r++)
                a += hc[wid * 256 + lane + 32 * r] * vreg[lane + 32 * r];
#pragma unroll
            for (int o = 16; o; o >>= 1) a += __shfl_xor_sync(0xffffffffu, a, o);
            if (lane == 0)
                out[(size_t)(bid * G + wid) * TDEC + (sd - (DSTEPS - TDEC))] = a + vreg[130];
        }
    }
}

// ---------------- launch ----------------
extern "C" void kernel_launch(void* const* d_in, const int* in_sizes, int n_in,
                              void* d_out, int out_size) {
    const float* input_p_q = (const float*)d_in[0];
    const float* label_p   = (const float*)d_in[1];
    const float* Ue1_W = (const float*)d_in[2];
    const float* Ue1_b = (const float*)d_in[3];
    const float* We1_W = (const float*)d_in[4];
    const float* Ve1_W = (const float*)d_in[5];
    const float* Ve1_b = (const float*)d_in[6];
    const float* Ue2_W = (const float*)d_in[7];
    const float* Ue2_b = (const float*)d_in[8];
    const float* We2_W = (const float*)d_in[9];
    const float* Ve2_W = (const float*)d_in[10];
    const float* Ve2_b = (const float*)d_in[11];
    const float* Ud_W  = (const float*)d_in[12];
    const float* Ud_b  = (const float*)d_in[13];
    const float* Wd_W  = (const float*)d_in[14];
    const float* Vd_W  = (const float*)d_in[15];
    const float* Vd_b  = (const float*)d_in[16];
    const float* e1_Wih = (const float*)d_in[17];
    const float* e1_Whh = (const float*)d_in[18];
    const float* e1_bih = (const float*)d_in[19];
    const float* e1_bhh = (const float*)d_in[20];
    const float* e2_Wih = (const float*)d_in[21];
    const float* e2_Whh = (const float*)d_in[22];
    const float* e2_bih = (const float*)d_in[23];
    const float* e2_bhh = (const float*)d_in[24];
    const float* d_Wih  = (const float*)d_in[25];
    const float* d_Whh  = (const float*)d_in[26];
    const float* d_bih  = (const float*)d_in[27];
    const float* d_bhh  = (const float*)d_in[28];
    const float* reg_W  = (const float*)d_in[29];
    const float* reg_b  = (const float*)d_in[30];
    float* out = (float*)d_out;

    __nv_bfloat16 *p_WtB1, *p_WtB2;
    float *p_Wet1, *p_Wet2;
    float *p_b1, *p_b2, *p_pre1, *p_mid, *p_fin;
    cudaGetSymbolAddress((void**)&p_WtB1, g_WtB1);
    cudaGetSymbolAddress((void**)&p_WtB2, g_WtB2);
    cudaGetSymbolAddress((void**)&p_Wet1, g_Wet1);
    cudaGetSymbolAddress((void**)&p_Wet2, g_Wet2);
    cudaGetSymbolAddress((void**)&p_b1, g_b1);
    cudaGetSymbolAddress((void**)&p_b2, g_b2);
    cudaGetSymbolAddress((void**)&p_pre1, g_pre1);
    cudaGetSymbolAddress((void**)&p_mid, g_mid);
    cudaGetSymbolAddress((void**)&p_fin, g_fin);

    const int STAGE1_SMEM = 43016 * 4;
    const int STAGE2_SMEM = 55624 * 4;
    const int DEC_SMEM    = DEC_SMEM_FL * 4;
    const int UD_SMEM     = (16384 + TENC * 129) * 4;

    cudaFuncSetAttribute((const void*)stage_kernel<K1, KP1, NF1, false>,
                         cudaFuncAttributeMaxDynamicSharedMemorySize, STAGE1_SMEM);
    cudaFuncSetAttribute((const void*)stage_kernel<K2, KP2, NF2, true>,
                         cudaFuncAttributeMaxDynamicSharedMemorySize, STAGE2_SMEM);
    cudaFuncSetAttribute((const void*)decoder_kernel,
                         cudaFuncAttributeMaxDynamicSharedMemorySize, DEC_SMEM);
    cudaFuncSetAttribute((const void*)ud_kernel,
                         cudaFuncAttributeMaxDynamicSharedMemorySize, UD_SMEM);

    setup_kernel<<<128, 256>>>(e1_Wih, e1_Whh, e2_Wih, e2_Whh, d_Wih, d_Whh,
                               We1_W, We2_W, Wd_W, Ud_W,
                               e1_bih, e1_bhh, e2_bih, e2_bhh, d_bih, d_bhh);
    pre1_kernel<<<BTOT, 256>>>(input_p_q, label_p, Ue1_W, Ue1_b);
    stage_kernel<K1, KP1, NF1, false><<<NCTA, NTH, STAGE1_SMEM>>>(
        input_p_q, Ve1_W, Ve1_b, p_WtB1, p_b1, p_Wet1, p_pre1, p_mid, NF2);
    pre2_kernel<<<BTOT, 256>>>(Ue2_W, Ue2_b);
    stage_kernel<K2, KP2, NF2, true><<<NCTA, NTH, STAGE2_SMEM>>>(
        input_p_q, Ve2_W, Ve2_b, p_WtB2, p_b2, p_Wet2, nullptr, p_fin, HD);
    ud_kernel<<<BTOT, 256, UD_SMEM>>>(Ud_b);
    decoder_kernel<<<NCTA, NTH, DEC_SMEM>>>(Vd_W, Vd_b, reg_W, reg_b, out);
}

// round 6
// speedup vs baseline: 2.1142x; 1.1587x over previous
#include <cuda_runtime.h>
#include <cuda_bf16.h>

#define TENC 48
#define TDEC 24
#define DSTEPS 30
#define HD 128
#define NF1 17
#define NF2 129
#define K1 145
#define KP1 160
#define K2 257
#define KP2 272
#define KD 256
#define KPD 256
#define G 8
#define NCTA 128
#define NTH 512
#define NG 512
#define BTOT 1024
#define HCT_STR 10

typedef unsigned long long u64;

// ---------------- device scratch (allocation-free) ----------------
__device__ __nv_bfloat16 g_WtB1[KP1 * NG];    // [k][n] bf16, zero-padded k
__device__ __nv_bfloat16 g_WtB2[KP2 * NG];
__device__ __nv_bfloat16 g_WtBd[KPD * NG];
__device__ float g_Wet1[256 * TENC];
__device__ float g_Wet2[256 * TENC];
__device__ float g_Wdt[256 * HD];             // [k][j]
__device__ float g_Udt[HD * HD];
__device__ float g_b1[NG], g_b2[NG], g_bd[NG];
__device__ float g_pre1[BTOT * TENC * NF1];           // [b][s][f] fp32
__device__ __nv_bfloat16 g_pre2h[BTOT * TENC * NF2];  // [b][s][f] bf16
__device__ float g_mid[BTOT * TENC * NF2];            // [b][t][f] (f=128 label)
__device__ float g_fin[BTOT * TENC * HD];             // [b][t][j]
__device__ __nv_bfloat16 g_udTh[BTOT * HD * TENC];    // [b][j][t] bf16

// ---------------- math helpers ----------------
__device__ __forceinline__ float tanha(float x) {
    float y; asm("tanh.approx.f32 %0, %1;" : "=f"(y) : "f"(x)); return y;
}
__device__ __forceinline__ float siga(float x) {
    return fmaf(tanha(0.5f * x), 0.5f, 0.5f);
}
__device__ __forceinline__ u64 fma2(u64 a, u64 b, u64 c) {
    u64 d; asm("fma.rn.f32x2 %0, %1, %2, %3;" : "=l"(d) : "l"(a), "l"(b), "l"(c)); return d;
}
__device__ __forceinline__ u64 dup2(float x) {
    u64 d; unsigned r = __float_as_uint(x);
    asm("mov.b64 %0, {%1, %1};" : "=l"(d) : "r"(r)); return d;
}
__device__ __forceinline__ float2 unpack2(u64 a) {
    unsigned l, h;
    asm("mov.b64 {%0, %1}, %2;" : "=r"(l), "=r"(h) : "l"(a));
    return make_float2(__uint_as_float(l), __uint_as_float(h));
}

__device__ __forceinline__ void warp_softmax(const float* score_row, float* alpha_row,
                                             int F, int lane) {
    float mx = -1e30f;
    for (int f = lane; f < F; f += 32) mx = fmaxf(mx, score_row[f]);
#pragma unroll
    for (int o = 16; o; o >>= 1) mx = fmaxf(mx, __shfl_xor_sync(0xffffffffu, mx, o));
    float sm = 0.f;
    for (int f = lane; f < F; f += 32) {
        float e = __expf(score_row[f] - mx);
        alpha_row[f] = e;
        sm += e;
    }
#pragma unroll
    for (int o = 16; o; o >>= 1) sm += __shfl_xor_sync(0xffffffffu, sm, o);
    float inv = __fdividef(1.f, sm);
    for (int f = lane; f < F; f += 32) alpha_row[f] *= inv;
}

// gate GEMM: [k][n]-major bf16 weights, K split across thread halves,
// explicit 8-deep weight prefetch for MLP.
template <int KP>
__device__ __forceinline__ void gates_gemm4(const __nv_bfloat16* __restrict__ WtB,
                                            const float* __restrict__ bias,
                                            const float* __restrict__ inpair,
                                            float* __restrict__ gates,
                                            float* __restrict__ pg, int tid) {
    constexpr int KH = KP / 2;
    static_assert(KH % 8 == 0, "KH must be multiple of 8");
    const int half = tid >> 8;
    const int lt = tid & 255;
    const int n0 = lt * 2;
    const int k0 = half * KH;
    u64 a0 = 0, a1 = 0, a2 = 0, a3 = 0, a4 = 0, a5 = 0, a6 = 0, a7 = 0;
    const unsigned* wpu = (const unsigned*)(WtB + (size_t)k0 * NG + n0);
    const float* ipp = inpair + k0 * G;
#pragma unroll 1
    for (int kk = 0; kk < KH; kk += 8) {
        unsigned rw[8];
#pragma unroll
        for (int i = 0; i < 8; i++) rw[i] = wpu[(size_t)(kk + i) * (NG / 2)];
#pragma unroll
        for (int i = 0; i < 8; i++) {
            float2 wf = __bfloat1622float2(*(const __nv_bfloat162*)&rw[i]);
            u64 w0 = dup2(wf.x), w1 = dup2(wf.y);
            const float* ip = ipp + (kk + i) * G;
            ulonglong2 iab = *(const ulonglong2*)ip;
            ulonglong2 icd = *(const ulonglong2*)(ip + 4);
            a0 = fma2(w0, iab.x, a0); a1 = fma2(w0, iab.y, a1);
            a2 = fma2(w0, icd.x, a2); a3 = fma2(w0, icd.y, a3);
            a4 = fma2(w1, iab.x, a4); a5 = fma2(w1, iab.y, a5);
            a6 = fma2(w1, icd.x, a6); a7 = fma2(w1, icd.y, a7);
        }
    }
    if (half) {
        float* pp = pg + n0 * 9;
        float2 r;
        r = unpack2(a0); pp[0] = r.x; pp[1] = r.y;
        r = unpack2(a1); pp[2] = r.x; pp[3] = r.y;
        r = unpack2(a2); pp[4] = r.x; pp[5] = r.y;
        r = unpack2(a3); pp[6] = r.x; pp[7] = r.y;
        pp += 9;
        r = unpack2(a4); pp[0] = r.x; pp[1] = r.y;
        r = unpack2(a5); pp[2] = r.x; pp[3] = r.y;
        r = unpack2(a6); pp[4] = r.x; pp[5] = r.y;
        r = unpack2(a7); pp[6] = r.x; pp[7] = r.y;
    }
    __syncthreads();
    if (!half) {
        const float* pp = pg + n0 * 9;
        const float* pq = pp + 9;
        float b0 = bias[n0], b1 = bias[n0 + 1];
        float2 r;
        r = unpack2(a0); gates[0*NG+n0] = r.x + pp[0] + b0; gates[1*NG+n0] = r.y + pp[1] + b0;
        r = unpack2(a1); gates[2*NG+n0] = r.x + pp[2] + b0; gates[3*NG+n0] = r.y + pp[3] + b0;
        r = unpack2(a2); gates[4*NG+n0] = r.x + pp[4] + b0; gates[5*NG+n0] = r.y + pp[5] + b0;
        r = unpack2(a3); gates[6*NG+n0] = r.x + pp[6] + b0; gates[7*NG+n0] = r.y + pp[7] + b0;
        r = unpack2(a4); gates[0*NG+n0+1] = r.x + pq[0] + b1; gates[1*NG+n0+1] = r.y + pq[1] + b1;
        r = unpack2(a5); gates[2*NG+n0+1] = r.x + pq[2] + b1; gates[3*NG+n0+1] = r.y + pq[3] + b1;
        r = unpack2(a6); gates[4*NG+n0+1] = r.x + pq[4] + b1; gates[5*NG+n0+1] = r.y + pq[5] + b1;
        r = unpack2(a7); gates[6*NG+n0+1] = r.x + pq[6] + b1; gates[7*NG+n0+1] = r.y + pq[7] + b1;
    }
}

// ---------------- setup ----------------
__global__ void setup_kernel(
    const float* __restrict__ e1_Wih, const float* __restrict__ e1_Whh,
    const float* __restrict__ e2_Wih, const float* __restrict__ e2_Whh,
    const float* __restrict__ d_Wih,  const float* __restrict__ d_Whh,
    const float* __restrict__ We1,    const float* __restrict__ We2,
    const float* __restrict__ Wd,     const float* __restrict__ Ud,
    const float* __restrict__ e1_bih, const float* __restrict__ e1_bhh,
    const float* __restrict__ e2_bih, const float* __restrict__ e2_bhh,
    const float* __restrict__ d_bih,  const float* __restrict__ d_bhh) {
    int tid = blockIdx.x * blockDim.x + threadIdx.x;
    int nt = gridDim.x * blockDim.x;
    for (int i = tid; i < KP1 * NG; i += nt) {
        int k = i / NG, n = i % NG;
        float v = 0.f;
        if (k < K1) v = (k < NF1) ? e1_Wih[n * NF1 + k] : e1_Whh[n * HD + (k - NF1)];
        g_WtB1[i] = __float2bfloat16(v);
    }
    for (int i = tid; i < KP2 * NG; i += nt) {
        int k = i / NG, n = i % NG;
        float v = 0.f;
        if (k < K2) v = (k < NF2) ? e2_Wih[n * NF2 + k] : e2_Whh[n * HD + (k - NF2)];
        g_WtB2[i] = __float2bfloat16(v);
    }
    for (int i = tid; i < KPD * NG; i += nt) {
        int k = i / NG, n = i % NG;
        float v = (k < HD) ? d_Wih[n * HD + k] : d_Whh[n * HD + (k - HD)];
        g_WtBd[i] = __float2bfloat16(v);
    }
    for (int i = tid; i < 256 * TENC; i += nt) {
        int k = i / TENC, ss = i % TENC;
        g_Wet1[i] = We1[ss * 256 + k];
        g_Wet2[i] = We2[ss * 256 + k];
    }
    for (int i = tid; i < 256 * HD; i += nt) {
        int k = i / HD, j = i % HD;
        g_Wdt[i] = Wd[j * 256 + k];
    }
    for (int i = tid; i < HD * HD; i += nt) {
        int k = i / HD, j = i % HD;
        g_Udt[i] = Ud[j * HD + k];
    }
    for (int i = tid; i < NG; i += nt) {
        g_b1[i] = e1_bih[i] + e1_bhh[i];
        g_b2[i] = e2_bih[i] + e2_bhh[i];
        g_bd[i] = d_bih[i] + d_bhh[i];
    }
}

// ---------------- pre1 ----------------
__global__ __launch_bounds__(256) void pre1_kernel(
    const float* __restrict__ inp, const float* __restrict__ lab,
    const float* __restrict__ Ue1, const float* __restrict__ Ue1b) {
    __shared__ float xs[TENC * NF1];
    __shared__ float ue[TENC * TENC];
    int b = blockIdx.x, tid = threadIdx.x;
    for (int i = tid; i < TENC * NF1; i += 256) {
        int t = i / NF1, f = i % NF1;
        xs[i] = inp[((size_t)b * TENC + t) * 18 + f + 1];
    }
    for (int i = tid; i < TENC * TENC; i += 256) ue[i] = Ue1[i];
    for (int i = tid; i < TENC; i += 256)
        g_mid[((size_t)b * TENC + i) * NF2 + HD] = lab[(size_t)b * TENC + i];
    __syncthreads();
    for (int i = tid; i < TENC * NF1; i += 256) {
        int ss = i / NF1, f = i % NF1;
        float a = 0.f;
#pragma unroll 8
        for (int t = 0; t < TENC; t++) a += xs[t * NF1 + f] * ue[ss * TENC + t];
        g_pre1[(size_t)b * TENC * NF1 + i] = a + Ue1b[ss];
    }
}

// ---------------- pre2 (bf16 out, f32x2 pairs) ----------------
__global__ __launch_bounds__(256) void pre2_kernel(
    const float* __restrict__ Ue2, const float* __restrict__ Ue2b) {
    __shared__ float ms[TENC * 130];
    __shared__ float ue[TENC * TENC];
    int b = blockIdx.x, tid = threadIdx.x;
    for (int i = tid; i < TENC * NF2; i += 256) {
        int t = i / NF2, f = i % NF2;
        ms[t * 130 + f] = g_mid[(size_t)b * TENC * NF2 + i];
    }
    for (int i = tid; i < TENC; i += 256) ms[i * 130 + 129] = 0.f;
    for (int i = tid; i < TENC * TENC; i += 256) ue[i] = Ue2[i];
    __syncthreads();
    for (int u = tid; u < TENC * 65; u += 256) {
        int ss = u / 65, q = u % 65;
        int f0 = 2 * q;
        u64 acc = 0ull;
#pragma unroll 8
        for (int t = 0; t < TENC; t++)
            acc = fma2(dup2(ue[ss * TENC + t]), *(const u64*)(ms + t * 130 + f0), acc);
        float2 r = unpack2(acc);
        float bb = Ue2b[ss];
        size_t base = (size_t)b * TENC * NF2 + ss * NF2;
        g_pre2h[base + f0] = __float2bfloat16(r.x + bb);
        if (f0 < 128) g_pre2h[base + f0 + 1] = __float2bfloat16(r.y + bb);
    }
}

// ---------------- ud (bf16 out, transposed) ----------------
__global__ __launch_bounds__(256) void ud_kernel(const float* __restrict__ Udb) {
    extern __shared__ float sm_ud[];
    float* udt = sm_ud;
    float* fs  = sm_ud + 16384;
    int b = blockIdx.x, tid = threadIdx.x;
    for (int i = tid; i < HD * HD; i += 256) udt[i] = g_Udt[i];
    for (int i = tid; i < TENC * HD; i += 256) {
        int t = i >> 7, k = i & 127;
        fs[t * 129 + k] = g_fin[(size_t)b * TENC * HD + i];
    }
    __syncthreads();
    for (int u = tid; u < 32 * TENC; u += 256) {
        int t = u % TENC, jq = u / TENC;
        int j0 = 4 * jq;
        float a0 = Udb[j0], a1 = Udb[j0 + 1], a2 = Udb[j0 + 2], a3 = Udb[j0 + 3];
#pragma unroll 8
        for (int k = 0; k < HD; k++) {
            float f = fs[t * 129 + k];
            float4 uu = *(const float4*)(udt + k * HD + j0);
            a0 += f * uu.x; a1 += f * uu.y; a2 += f * uu.z; a3 += f * uu.w;
        }
        size_t base = (size_t)b * HD * TENC;
        g_udTh[base + (size_t)(j0 + 0) * TENC + t] = __float2bfloat16(a0);
        g_udTh[base + (size_t)(j0 + 1) * TENC + t] = __float2bfloat16(a1);
        g_udTh[base + (size_t)(j0 + 2) * TENC + t] = __float2bfloat16(a2);
        g_udTh[base + (size_t)(j0 + 3) * TENC + t] = __float2bfloat16(a3);
    }
}

// ---------------- encoder stage (templated) ----------------
template <int K, int KP, int NF, bool PB16>
__global__ __launch_bounds__(NTH, 1) void stage_kernel(
    const float* __restrict__ inp,
    const float* __restrict__ Ve, const float* __restrict__ Veb,
    const __nv_bfloat16* __restrict__ WtB, const float* __restrict__ bsum,
    const float* __restrict__ Wet, const float* __restrict__ preF,
    float* __restrict__ outb, int ostride) {
    extern __shared__ float sm[];
    constexpr int PRE_FL = PB16 ? (G * TENC * NF / 2) : (G * TENC * NF);
    constexpr int XS_FL  = PB16 ? 0 : (G * TENC * NF1);
    constexpr int O_PRE = 12288;
    constexpr int O_XS  = O_PRE + PRE_FL;
    constexpr int O_HC  = O_XS + XS_FL;
    constexpr int O_HCT = O_HC + 2048;
    constexpr int O_WE  = O_HCT + 256 * HCT_STR;
    constexpr int O_WEP = O_WE + 384;
    constexpr int O_SC  = O_WEP + 384;
    constexpr int O_AL  = O_SC + 1056;
    constexpr int O_IP  = O_AL + 1056;
    constexpr int O_GT  = O_IP + KP * 8;
    constexpr int O_PG  = O_GT + 4096;
    constexpr int O_BS  = O_PG + 4608;
    constexpr int O_VV  = O_BS + 512;

    float* wet    = sm;
    float* pres   = sm + O_PRE;
    float* xs     = sm + O_XS;
    float* hc     = sm + O_HC;
    float* hcT    = sm + O_HCT;
    float* we     = sm + O_WE;
    float* wepart = sm + O_WEP;
    float* score  = sm + O_SC;
    float* alpha  = sm + O_AL;
    float* inpair = sm + O_IP;
    float* gates  = sm + O_GT;
    float* pg     = sm + O_PG;
    float* bias   = sm + O_BS;
    float* vvec   = sm + O_VV;

    const int tid = threadIdx.x, bid = blockIdx.x;
    const int wid = tid >> 5, lane = tid & 31;

    for (int i = tid; i < 256 * TENC; i += NTH) wet[i] = Wet[i];
    if (PB16) {
        const unsigned* src = (const unsigned*)(g_pre2h + (size_t)bid * G * TENC * NF2);
        unsigned* dst = (unsigned*)pres;
        for (int i = tid; i < G * TENC * NF2 / 2; i += NTH) dst[i] = src[i];
    } else {
        const float* src = preF + (size_t)bid * G * TENC * NF;
        for (int i = tid; i < G * TENC * NF; i += NTH) pres[i] = src[i];
        for (int i = tid; i < G * TENC * NF1; i += NTH) {
            int g = i / (TENC * NF1);
            int r = i - g * TENC * NF1;
            int t = r / NF1, f = r - t * NF1;
            xs[i] = inp[((size_t)(bid * G + g) * TENC + t) * 18 + f + 1];
        }
    }
    for (int i = tid; i < G * 256; i += NTH) hc[i] = 0.f;
    for (int i = tid; i < 256 * HCT_STR; i += NTH) hcT[i] = 0.f;
    for (int i = tid; i < NG; i += NTH) bias[i] = bsum[i];
    for (int i = tid; i < TENC; i += NTH) vvec[i] = Ve[i];
    if (tid == 0) vvec[130] = Veb[0];
    for (int i = tid; i < KP * G; i += NTH) inpair[i] = 0.f;
    __syncthreads();

    const int NITEM = G * NF;
    int i0 = tid, i1 = tid + NTH, i2 = tid + 2 * NTH;
    bool v0 = i0 < NITEM, v1 = i1 < NITEM, v2 = i2 < NITEM;
    int g0 = v0 ? i0 / NF : 0, f0 = v0 ? i0 % NF : 0;
    int g1 = v1 ? i1 / NF : 0, f1 = v1 ? i1 % NF : 0;
    int g2 = v2 ? i2 / NF : 0, f2 = v2 ? i2 % NF : 0;

    for (int t = 0; t < TENC; t++) {
        // A: we projection, 2-way k split over 384 threads
        if (tid < 384) {
            int half = (tid >= 192) ? 1 : 0;
            int t2 = tid - 192 * half;
            int p = t2 / TENC, ss = t2 - p * TENC;
            int kb = half * 128;
            u64 acc = 0ull;
#pragma unroll 8
            for (int kk = 0; kk < 128; kk++) {
                int k = kb + kk;
                u64 h2 = *(const u64*)(hcT + k * HCT_STR + 2 * p);
                acc = fma2(dup2(wet[k * TENC + ss]), h2, acc);
            }
            float2 v = unpack2(acc);
            float* dst = half ? wepart : we;
            dst[(2 * p) * TENC + ss] = v.x;
            dst[(2 * p + 1) * TENC + ss] = v.y;
        }
        __syncthreads();
        if (tid < 384) we[tid] += wepart[tid];
        __syncthreads();
        // B: scores from smem
        {
            float a0 = 0.f, a1 = 0.f, a2 = 0.f;
            if (PB16) {
                const __nv_bfloat16* ph = (const __nv_bfloat16*)pres;
                const __nv_bfloat16* p0 = ph + g0 * TENC * NF + f0;
                const __nv_bfloat16* p1 = ph + g1 * TENC * NF + f1;
                const __nv_bfloat16* p2 = ph + g2 * TENC * NF + f2;
#pragma unroll 4
                for (int ss = 0; ss < TENC; ss++) {
                    float vv = vvec[ss];
                    if (v0) a0 += tanha(we[g0 * TENC + ss] + __bfloat162float(p0[ss * NF])) * vv;
                    if (v1) a1 += tanha(we[g1 * TENC + ss] + __bfloat162float(p1[ss * NF])) * vv;
                    if (v2) a2 += tanha(we[g2 * TENC + ss] + __bfloat162float(p2[ss * NF])) * vv;
                }
            } else {
                const float* p0 = pres + g0 * TENC * NF + f0;
                const float* p1 = pres + g1 * TENC * NF + f1;
                const float* p2 = pres + g2 * TENC * NF + f2;
#pragma unroll 4
                for (int ss = 0; ss < TENC; ss++) {
                    float vv = vvec[ss];
                    if (v0) a0 += tanha(we[g0 * TENC + ss] + p0[ss * NF]) * vv;
                    if (v1) a1 += tanha(we[g1 * TENC + ss] + p1[ss * NF]) * vv;
                    if (v2) a2 += tanha(we[g2 * TENC + ss] + p2[ss * NF]) * vv;
                }
            }
            float bb = vvec[130];
            if (v0) score[g0 * 132 + f0] = a0 + bb;
            if (v1) score[g1 * 132 + f1] = a1 + bb;
            if (v2) score[g2 * 132 + f2] = a2 + bb;
        }
        __syncthreads();
        if (wid < G) warp_softmax(score + wid * 132, alpha + wid * 132, NF, lane);
        __syncthreads();
        // D: gate inputs (x part only; h part maintained in F)
        for (int idx = tid; idx < NF * G; idx += NTH) {
            int k = idx >> 3, g = idx & 7;
            float xv;
            if (PB16) xv = g_mid[((size_t)(bid * G + g) * TENC + t) * NF2 + k];
            else      xv = xs[g * TENC * NF1 + t * NF1 + k];
            inpair[k * G + g] = xv * alpha[g * 132 + k];
        }
        __syncthreads();
        gates_gemm4<KP>(WtB, bias, inpair, gates, pg, tid);
        __syncthreads();
        // F: cell update + output h + next-step inpair h rows
        for (int idx = tid; idx < G * HD; idx += NTH) {
            int g = idx >> 7, j = idx & 127;
            float gi = gates[g * NG + j];
            float gf = gates[g * NG + HD + j];
            float gg = gates[g * NG + 2 * HD + j];
            float go = gates[g * NG + 3 * HD + j];
            float c  = hc[g * 256 + HD + j];
            float c2 = siga(gf) * c + siga(gi) * tanha(gg);
            float h  = siga(go) * tanha(c2);
            hc[g * 256 + j] = h;
            hc[g * 256 + HD + j] = c2;
            hcT[j * HCT_STR + g] = h;
            hcT[(128 + j) * HCT_STR + g] = c2;
            inpair[(NF + j) * G + g] = h;
            outb[((size_t)(bid * G + g) * TENC + t) * ostride + j] = h;
        }
        __syncthreads();
    }
}

// ---------------- decoder ----------------
#define D_O_WDT 0
#define D_O_HC  32768
#define D_O_HCT 34816
#define D_O_WD  37376
#define D_O_SC  38400
#define D_O_AL  38784
#define D_O_IP  39168
#define D_O_GT  41216
#define D_O_PG  45312
#define D_O_BS  49920
#define D_O_VV  50432
#define D_O_VR  50568
#define DEC_SMEM_FL 50704

__global__ __launch_bounds__(NTH, 1) void decoder_kernel(
    const float* __restrict__ Vd, const float* __restrict__ Vdb,
    const float* __restrict__ regW, const float* __restrict__ regb,
    float* __restrict__ out) {
    extern __shared__ float sm[];
    float* wdt    = sm + D_O_WDT;
    float* hc     = sm + D_O_HC;
    float* hcT    = sm + D_O_HCT;
    float* wd     = sm + D_O_WD;
    float* score  = sm + D_O_SC;
    float* alpha  = sm + D_O_AL;
    float* inpair = sm + D_O_IP;
    float* gates  = sm + D_O_GT;
    float* pg     = sm + D_O_PG;
    float* bias   = sm + D_O_BS;
    float* vvec   = sm + D_O_VV;
    float* vreg   = sm + D_O_VR;
    float* part   = gates;   // 8192 floats spanning gates+pg, free during phase A

    const int tid = threadIdx.x, bid = blockIdx.x;
    const int wid = tid >> 5, lane = tid & 31;

    for (int i = tid; i < 256 * HD; i += NTH) wdt[i] = g_Wdt[i];
    for (int i = tid; i < G * 256; i += NTH) hc[i] = 0.f;
    for (int i = tid; i < 256 * HCT_STR; i += NTH) hcT[i] = 0.f;
    for (int i = tid; i < NG; i += NTH) bias[i] = g_bd[i];
    for (int i = tid; i < KPD * G; i += NTH) inpair[i] = 0.f;
    for (int i = tid; i < HD; i += NTH) { vvec[i] = Vd[i]; vreg[i] = regW[i]; }
    if (tid == 0) { vvec[130] = Vdb[0]; vreg[130] = regb[0]; }
    __syncthreads();

    bool sval = tid < G * TENC;
    int sg = sval ? tid / TENC : 0, stt = sval ? tid % TENC : 0;
    const __nv_bfloat16* up = g_udTh + ((size_t)(bid * G + sg) * HD) * TENC + stt;
    int dg = tid >> 6, dj = (tid & 63) * 2;
    const float* fp = g_fin + ((size_t)(bid * G + dg) * TENC) * HD + dj;
    // phase-A mapping: 8-way k split
    const int s8 = tid >> 6;           // 0..7, k slice
    const int jp = tid & 63, j0 = 2 * jp;

    for (int sd = 0; sd < DSTEPS; sd++) {
        // A: wd projection as mini-GEMM with 8-way k split
        {
            u64 a0 = 0, a1 = 0, a2 = 0, a3 = 0, a4 = 0, a5 = 0, a6 = 0, a7 = 0;
            int kb = s8 * 32;
#pragma unroll 8
            for (int kk = 0; kk < 32; kk++) {
                int k = kb + kk;
                float2 w = *(const float2*)(wdt + k * HD + j0);
                u64 w0 = dup2(w.x), w1 = dup2(w.y);
                const float* hp = hcT + k * HCT_STR;
                u64 h01 = *(const u64*)(hp);
                u64 h23 = *(const u64*)(hp + 2);
                u64 h45 = *(const u64*)(hp + 4);
                u64 h67 = *(const u64*)(hp + 6);
                a0 = fma2(w0, h01, a0); a1 = fma2(w0, h23, a1);
                a2 = fma2(w0, h45, a2); a3 = fma2(w0, h67, a3);
                a4 = fma2(w1, h01, a4); a5 = fma2(w1, h23, a5);
                a6 = fma2(w1, h45, a6); a7 = fma2(w1, h67, a7);
            }
            float* pp = part + s8 * 1024 + j0 * 8;
            float2 r;
            r = unpack2(a0); pp[0] = r.x; pp[1] = r.y;
            r = unpack2(a1); pp[2] = r.x; pp[3] = r.y;
            r = unpack2(a2); pp[4] = r.x; pp[5] = r.y;
            r = unpack2(a3); pp[6] = r.x; pp[7] = r.y;
            pp += 8;
            r = unpack2(a4); pp[0] = r.x; pp[1] = r.y;
            r = unpack2(a5); pp[2] = r.x; pp[3] = r.y;
            r = unpack2(a6); pp[4] = r.x; pp[5] = r.y;
            r = unpack2(a7); pp[6] = r.x; pp[7] = r.y;
        }
        __syncthreads();
#pragma unroll
        for (int u = 0; u < 2; u++) {
            int o = tid + u * NTH;
            float s = 0.f;
#pragma unroll
            for (int q = 0; q < 8; q++) s += part[q * 1024 + o];
            int j = o >> 3, g = o & 7;
            wd[g * HD + j] = s;
        }
        __syncthreads();
        // B: score from global bf16 udT + smem wd
        {
            float a = 0.f;
#pragma unroll 4
            for (int j = 0; j < HD; j++)
                a += tanha(wd[sg * HD + j] + __bfloat162float(up[(size_t)j * TENC])) * vvec[j];
            if (sval) score[sg * TENC + stt] = a + vvec[130];
        }
        __syncthreads();
        if (wid < G) warp_softmax(score + wid * TENC, alpha + wid * TENC, TENC, lane);
        __syncthreads();
        // D: din (h rows maintained in F)
        {
            float a0 = 0.f, a1 = 0.f;
#pragma unroll 4
            for (int tt = 0; tt < TENC; tt++) {
                float al = alpha[dg * TENC + tt];
                float2 f2 = *(const float2*)(fp + (size_t)tt * HD);
                a0 += al * f2.x; a1 += al * f2.y;
            }
            inpair[dj * G + dg] = a0;
            inpair[(dj + 1) * G + dg] = a1;
        }
        __syncthreads();
        gates_gemm4<KPD>(g_WtBd, bias, inpair, gates, pg, tid);
        __syncthreads();
        // F: cell + next-step inpair h rows
        for (int idx = tid; idx < G * HD; idx += NTH) {
            int g = idx >> 7, j = idx & 127;
            float gi = gates[g * NG + j];
            float gf = gates[g * NG + HD + j];
            float gg = gates[g * NG + 2 * HD + j];
            float go = gates[g * NG + 3 * HD + j];
            float c  = hc[g * 256 + HD + j];
            float c2 = siga(gf) * c + siga(gi) * tanha(gg);
            float h  = siga(go) * tanha(c2);
            hc[g * 256 + j] = h;
            hc[g * 256 + HD + j] = c2;
            hcT[j * HCT_STR + g] = h;
            hcT[(128 + j) * HCT_STR + g] = c2;
            inpair[(HD + j) * G + g] = h;
        }
        __syncthreads();
        if (sd >= DSTEPS - TDEC && wid < G) {
            float a = 0.f;
#pragma unroll
            for (int r = 0; r < 4; r++)
                a += hc[wid * 256 + lane + 32 * r] * vreg[lane + 32 * r];
#pragma unroll
            for (int o = 16; o; o >>= 1) a += __shfl_xor_sync(0xffffffffu, a, o);
            if (lane == 0)
                out[(size_t)(bid * G + wid) * TDEC + (sd - (DSTEPS - TDEC))] = a + vreg[130];
        }
    }
}

// ---------------- launch ----------------
extern "C" void kernel_launch(void* const* d_in, const int* in_sizes, int n_in,
                              void* d_out, int out_size) {
    const float* input_p_q = (const float*)d_in[0];
    const float* label_p   = (const float*)d_in[1];
    const float* Ue1_W = (const float*)d_in[2];
    const float* Ue1_b = (const float*)d_in[3];
    const float* We1_W = (const float*)d_in[4];
    const float* Ve1_W = (const float*)d_in[5];
    const float* Ve1_b = (const float*)d_in[6];
    const float* Ue2_W = (const float*)d_in[7];
    const float* Ue2_b = (const float*)d_in[8];
    const float* We2_W = (const float*)d_in[9];
    const float* Ve2_W = (const float*)d_in[10];
    const float* Ve2_b = (const float*)d_in[11];
    const float* Ud_W  = (const float*)d_in[12];
    const float* Ud_b  = (const float*)d_in[13];
    const float* Wd_W  = (const float*)d_in[14];
    const float* Vd_W  = (const float*)d_in[15];
    const float* Vd_b  = (const float*)d_in[16];
    const float* e1_Wih = (const float*)d_in[17];
    const float* e1_Whh = (const float*)d_in[18];
    const float* e1_bih = (const float*)d_in[19];
    const float* e1_bhh = (const float*)d_in[20];
    const float* e2_Wih = (const float*)d_in[21];
    const float* e2_Whh = (const float*)d_in[22];
    const float* e2_bih = (const float*)d_in[23];
    const float* e2_bhh = (const float*)d_in[24];
    const float* d_Wih  = (const float*)d_in[25];
    const float* d_Whh  = (const float*)d_in[26];
    const float* d_bih  = (const float*)d_in[27];
    const float* d_bhh  = (const float*)d_in[28];
    const float* reg_W  = (const float*)d_in[29];
    const float* reg_b  = (const float*)d_in[30];
    float* out = (float*)d_out;

    __nv_bfloat16 *p_WtB1, *p_WtB2;
    float *p_Wet1, *p_Wet2;
    float *p_b1, *p_b2, *p_pre1, *p_mid, *p_fin;
    cudaGetSymbolAddress((void**)&p_WtB1, g_WtB1);
    cudaGetSymbolAddress((void**)&p_WtB2, g_WtB2);
    cudaGetSymbolAddress((void**)&p_Wet1, g_Wet1);
    cudaGetSymbolAddress((void**)&p_Wet2, g_Wet2);
    cudaGetSymbolAddress((void**)&p_b1, g_b1);
    cudaGetSymbolAddress((void**)&p_b2, g_b2);
    cudaGetSymbolAddress((void**)&p_pre1, g_pre1);
    cudaGetSymbolAddress((void**)&p_mid, g_mid);
    cudaGetSymbolAddress((void**)&p_fin, g_fin);

    const int STAGE1_SMEM = 43464 * 4;
    const int STAGE2_SMEM = 56072 * 4;
    const int DEC_SMEM    = DEC_SMEM_FL * 4;
    const int UD_SMEM     = (16384 + TENC * 129) * 4;

    cudaFuncSetAttribute((const void*)stage_kernel<K1, KP1, NF1, false>,
                         cudaFuncAttributeMaxDynamicSharedMemorySize, STAGE1_SMEM);
    cudaFuncSetAttribute((const void*)stage_kernel<K2, KP2, NF2, true>,
                         cudaFuncAttributeMaxDynamicSharedMemorySize, STAGE2_SMEM);
    cudaFuncSetAttribute((const void*)decoder_kernel,
                         cudaFuncAttributeMaxDynamicSharedMemorySize, DEC_SMEM);
    cudaFuncSetAttribute((const void*)ud_kernel,
                         cudaFuncAttributeMaxDynamicSharedMemorySize, UD_SMEM);

    setup_kernel<<<128, 256>>>(e1_Wih, e1_Whh, e2_Wih, e2_Whh, d_Wih, d_Whh,
                               We1_W, We2_W, Wd_W, Ud_W,
                               e1_bih, e1_bhh, e2_bih, e2_bhh, d_bih, d_bhh);
    pre1_kernel<<<BTOT, 256>>>(input_p_q, label_p, Ue1_W, Ue1_b);
    stage_kernel<K1, KP1, NF1, false><<<NCTA, NTH, STAGE1_SMEM>>>(
        input_p_q, Ve1_W, Ve1_b, p_WtB1, p_b1, p_Wet1, p_pre1, p_mid, NF2);
    pre2_kernel<<<BTOT, 256>>>(Ue2_W, Ue2_b);
    stage_kernel<K2, KP2, NF2, true><<<NCTA, NTH, STAGE2_SMEM>>>(
        input_p_q, Ve2_W, Ve2_b, p_WtB2, p_b2, p_Wet2, nullptr, p_fin, HD);
    ud_kernel<<<BTOT, 256, UD_SMEM>>>(Ud_b);
    decoder_kernel<<<NCTA, NTH, DEC_SMEM>>>(Vd_W, Vd_b, reg_W, reg_b, out);
}